// round 1
// baseline (speedup 1.0000x reference)
#include <cuda_runtime.h>

#define NQ      13
#define NL      2
#define DIM     (1 << NQ)          // 8192 amplitudes
#define THREADS 512
#define PER     (DIM / THREADS)    // 16 amplitudes owned per thread
#define PAIRS_PER_THREAD (DIM / 2 / THREADS)  // 8

__device__ __forceinline__ float2 cmul(float2 a, float2 b) {
    return make_float2(fmaf(a.x, b.x, -a.y * b.y),
                       fmaf(a.x, b.y,  a.y * b.x));
}
__device__ __forceinline__ float2 cadd(float2 a, float2 b) {
    return make_float2(a.x + b.x, a.y + b.y);
}

__global__ __launch_bounds__(THREADS, 1)
void qsim_kernel(const float* __restrict__ x,
                 const float* __restrict__ w,
                 float* __restrict__ out)
{
    extern __shared__ float2 s[];      // DIM complex amplitudes (64 KB)
    __shared__ float red[NQ];

    const int b = blockIdx.x;
    const int t = threadIdx.x;

    // init |0...0>
    #pragma unroll
    for (int k = 0; k < PER; k++) s[t + k * THREADS] = make_float2(0.f, 0.f);
    if (t == 0) s[0] = make_float2(1.f, 0.f);
    if (t < NQ) red[t] = 0.f;

    #pragma unroll
    for (int l = 0; l < NL; l++) {
        #pragma unroll
        for (int q = 0; q < NQ; q++) {
            // Fused U = RZ(phi) * RY(beta) * RX(alpha), computed redundantly per thread
            const float xv = x[b * NQ + q];
            const float* wr = w + (l * NQ + q) * 3;
            float s1, c1, s2, c2, sp, cp;
            sincosf(0.5f * xv * wr[0], &s1, &c1);   // RX half-angle
            sincosf(0.5f * xv * wr[1], &s2, &c2);   // RY half-angle
            sincosf(0.5f * wr[2],      &sp, &cp);   // RZ half-angle
            // M = RY*RX
            float2 m00 = make_float2( c2 * c1,  s2 * s1);
            float2 m01 = make_float2(-s2 * c1, -c2 * s1);
            float2 m10 = make_float2( s2 * c1, -c2 * s1);
            float2 m11 = make_float2( c2 * c1, -s2 * s1);
            // U = diag(e^{-i phi/2}, e^{+i phi/2}) * M
            const float2 e0 = make_float2(cp, -sp);
            const float2 e1 = make_float2(cp,  sp);
            const float2 U00 = cmul(e0, m00), U01 = cmul(e0, m01);
            const float2 U10 = cmul(e1, m10), U11 = cmul(e1, m11);

            const int shift = 12 - q;          // wire q's bit position in index
            const int mask  = 1 << shift;

            __syncthreads();
            #pragma unroll
            for (int it = 0; it < PAIRS_PER_THREAD; it++) {
                const int p  = t + it * THREADS;
                const int i0 = ((p >> shift) << (shift + 1)) | (p & (mask - 1));
                const int i1 = i0 | mask;
                const float2 a0 = s[i0];
                const float2 a1 = s[i1];
                s[i0] = cadd(cmul(U00, a0), cmul(U01, a1));
                s[i1] = cadd(cmul(U10, a0), cmul(U11, a1));
            }
        }

        // CNOT chain CNOT(i,i+1), i=0..11 == Gray-code permutation:
        // new[i] = old[i ^ (i>>1)]   (wire j bit sits at index bit 12-j)
        __syncthreads();
        float2 tmp[PER];
        #pragma unroll
        for (int k = 0; k < PER; k++) {
            const int i = t + k * THREADS;
            tmp[k] = s[i ^ (i >> 1)];
        }
        __syncthreads();
        #pragma unroll
        for (int k = 0; k < PER; k++)
            s[t + k * THREADS] = tmp[k];
    }

    // PauliZ expvals: ev[q] = sum_i |s[i]|^2 * (1 - 2*bit_{12-q}(i))
    __syncthreads();
    float ev[NQ];
    #pragma unroll
    for (int q = 0; q < NQ; q++) ev[q] = 0.f;

    #pragma unroll
    for (int k = 0; k < PER; k++) {
        const int i = t + k * THREADS;
        const float2 v = s[i];
        const float pr = fmaf(v.x, v.x, v.y * v.y);
        #pragma unroll
        for (int q = 0; q < NQ; q++)
            ev[q] += (i & (1 << (12 - q))) ? -pr : pr;
    }

    // warp reduce then one shared atomic per warp per wire
    #pragma unroll
    for (int q = 0; q < NQ; q++) {
        #pragma unroll
        for (int o = 16; o > 0; o >>= 1)
            ev[q] += __shfl_xor_sync(0xffffffffu, ev[q], o);
    }
    if ((t & 31) == 0) {
        #pragma unroll
        for (int q = 0; q < NQ; q++)
            atomicAdd(&red[q], ev[q]);
    }
    __syncthreads();
    if (t < NQ) out[b * NQ + t] = red[t];
}

extern "C" void kernel_launch(void* const* d_in, const int* in_sizes, int n_in,
                              void* d_out, int out_size)
{
    const float* x = (const float*)d_in[0];   // (B, 13) float32
    const float* w = (const float*)d_in[1];   // (2, 13, 3) float32
    float* out     = (float*)d_out;           // (B, 13) float32

    const int B = in_sizes[0] / NQ;
    const size_t smem = (size_t)DIM * sizeof(float2);   // 64 KB

    cudaFuncSetAttribute(qsim_kernel,
                         cudaFuncAttributeMaxDynamicSharedMemorySize,
                         (int)smem);
    qsim_kernel<<<B, THREADS, smem>>>(x, w, out);
}

// round 2
// speedup vs baseline: 2.9003x; 2.9003x over previous
#include <cuda_runtime.h>

#define NQ      13
#define NL      2
#define DIM     (1 << NQ)          // 8192 amplitudes
#define THREADS 512
#define PER     16                 // amps per thread

// XOR swizzle: spreads low-4 index bits with lane-ish bits -> <=2-phase LDS.64
__device__ __forceinline__ int swz(int i) { return i ^ ((i >> 4) & 0xF); }

// bit transpose: swap index bits 0..3 <-> 9..12, keep bits 4..8
__device__ __forceinline__ int bitT(int i) {
    return ((i & 0xF) << 9) | (i & 0x1F0) | ((i >> 9) & 0xF);
}

struct C2x2 { float2 u00, u01, u10, u11; };

__device__ __forceinline__ float2 cmul(float2 a, float2 b) {
    return make_float2(fmaf(a.x, b.x, -a.y * b.y),
                       fmaf(a.x, b.y,  a.y * b.x));
}
__device__ __forceinline__ float2 cmad(float2 acc, float2 a, float2 b) {
    acc.x = fmaf(a.x, b.x, fmaf(-a.y, b.y, acc.x));
    acc.y = fmaf(a.x, b.y, fmaf( a.y, b.x, acc.y));
    return acc;
}
__device__ __forceinline__ void gate_pair(float2& a0, float2& a1, const C2x2& U) {
    float2 n0 = cmul(U.u00, a0); n0 = cmad(n0, U.u01, a1);
    float2 n1 = cmul(U.u10, a0); n1 = cmad(n1, U.u11, a1);
    a0 = n0; a1 = n1;
}

__global__ __launch_bounds__(THREADS, 1)
void qsim_kernel(const float* __restrict__ x,
                 const float* __restrict__ w,
                 float* __restrict__ out)
{
    extern __shared__ float2 sbuf[];        // DIM float2 = 64 KB exchange buffer
    __shared__ float uG[NL * NQ][8];        // fused U per (layer,qubit)
    __shared__ float red[NQ];

    const int b    = blockIdx.x;
    const int t    = threadIdx.x;
    const int lane = t & 31;
    const int wid  = t >> 5;                // 0..15

    // ---- precompute all 26 fused U = RZ*RY*RX (one gate per thread) ----
    if (t < NL * NQ) {
        const int l = t / NQ, q = t % NQ;
        const float xv = x[b * NQ + q];
        const float* wr = w + (l * NQ + q) * 3;
        float s1, c1, s2, c2, sp, cp;
        sincosf(0.5f * xv * wr[0], &s1, &c1);   // RX
        sincosf(0.5f * xv * wr[1], &s2, &c2);   // RY
        sincosf(0.5f * wr[2],      &sp, &cp);   // RZ
        float2 m00 = make_float2( c2 * c1,  s2 * s1);
        float2 m01 = make_float2(-s2 * c1, -c2 * s1);
        float2 m10 = make_float2( s2 * c1, -c2 * s1);
        float2 m11 = make_float2( c2 * c1, -s2 * s1);
        const float2 e0 = make_float2(cp, -sp);
        const float2 e1 = make_float2(cp,  sp);
        float2 U00 = cmul(e0, m00), U01 = cmul(e0, m01);
        float2 U10 = cmul(e1, m10), U11 = cmul(e1, m11);
        uG[t][0] = U00.x; uG[t][1] = U00.y;
        uG[t][2] = U01.x; uG[t][3] = U01.y;
        uG[t][4] = U10.x; uG[t][5] = U10.y;
        uG[t][6] = U11.x; uG[t][7] = U11.y;
    }
    if (t < NQ) red[t] = 0.f;

    // ---- init |0>: global index 0 lives in thread 0, k=0 ----
    float2 r[PER];
    #pragma unroll
    for (int k = 0; k < PER; k++) r[k] = make_float2(0.f, 0.f);
    if (t == 0) r[0] = make_float2(1.f, 0.f);

    __syncthreads();   // uG ready

    #pragma unroll
    for (int l = 0; l < NL; l++) {
        // ---- wires 9..12: intra-thread register gates (index bits 3..0) ----
        #pragma unroll
        for (int q = 9; q < NQ; q++) {
            const float* ug = uG[l * NQ + q];
            C2x2 U = { {ug[0],ug[1]}, {ug[2],ug[3]}, {ug[4],ug[5]}, {ug[6],ug[7]} };
            const int beta = 12 - q;          // 3..0
            #pragma unroll
            for (int m = 0; m < 8; m++) {
                const int k0 = ((m >> beta) << (beta + 1)) | (m & ((1 << beta) - 1));
                const int k1 = k0 | (1 << beta);
                gate_pair(r[k0], r[k1], U);
            }
        }

        // ---- wires 4..8: lane-bit gates via shuffle (index bits 8..4) ----
        #pragma unroll
        for (int q = 4; q < 9; q++) {
            const float* ug = uG[l * NQ + q];
            C2x2 U = { {ug[0],ug[1]}, {ug[2],ug[3]}, {ug[4],ug[5]}, {ug[6],ug[7]} };
            const int lam = 8 - q;            // 4..0
            const int s   = (lane >> lam) & 1;
            const float2 um = s ? U.u11 : U.u00;   // coeff on my amp
            const float2 uo = s ? U.u10 : U.u01;   // coeff on partner amp
            #pragma unroll
            for (int k = 0; k < PER; k++) {
                float2 o;
                o.x = __shfl_xor_sync(0xffffffffu, r[k].x, 1 << lam);
                o.y = __shfl_xor_sync(0xffffffffu, r[k].y, 1 << lam);
                float2 n = cmul(um, r[k]);
                n = cmad(n, uo, o);
                r[k] = n;
            }
        }

        // ---- bit-transpose pass: u[i'] = v[T(i')] ----
        __syncthreads();
        #pragma unroll
        for (int k = 0; k < PER; k++) sbuf[swz((t << 4) | k)] = r[k];
        __syncthreads();
        #pragma unroll
        for (int k = 0; k < PER; k++) r[k] = sbuf[swz(bitT((t << 4) | k))];

        // ---- wires 0..3: now register gates on transposed bits (3-q) ----
        #pragma unroll
        for (int q = 0; q < 4; q++) {
            const float* ug = uG[l * NQ + q];
            C2x2 U = { {ug[0],ug[1]}, {ug[2],ug[3]}, {ug[4],ug[5]}, {ug[6],ug[7]} };
            const int beta = 3 - q;
            #pragma unroll
            for (int m = 0; m < 8; m++) {
                const int k0 = ((m >> beta) << (beta + 1)) | (m & ((1 << beta) - 1));
                const int k1 = k0 | (1 << beta);
                gate_pair(r[k0], r[k1], U);
            }
        }

        if (l == 0) {
            // ---- fused transpose-back + CNOT Gray perm:
            //      v_new[i] = u[T(i ^ (i>>1))] ----
            __syncthreads();
            #pragma unroll
            for (int k = 0; k < PER; k++) sbuf[swz((t << 4) | k)] = r[k];
            __syncthreads();
            #pragma unroll
            for (int k = 0; k < PER; k++) {
                const int i  = (t << 4) | k;
                const int gi = i ^ (i >> 1);
                r[k] = sbuf[swz(bitT(gi))];
            }
        }
    }

    // ---- expvals directly in transposed layout, folding the final CNOT
    //      perm into the signs. True pre-CNOT index j = T(i'):
    //      j bits: [12..9]=k, [8..4]=lane, [3..0]=wid.
    //      ev[q] sign = parity of bits 12..(12-q) of j (Gray decode). ----
    float ev[NQ];
    #pragma unroll
    for (int q = 0; q < NQ; q++) ev[q] = 0.f;

    #pragma unroll
    for (int k = 0; k < PER; k++) {
        const float2 v = r[k];
        const float pr = fmaf(v.x, v.x, v.y * v.y);
        int par = 0;
        par ^= (k >> 3) & 1;    ev[0]  += par ? -pr : pr;
        par ^= (k >> 2) & 1;    ev[1]  += par ? -pr : pr;
        par ^= (k >> 1) & 1;    ev[2]  += par ? -pr : pr;
        par ^=  k       & 1;    ev[3]  += par ? -pr : pr;
        par ^= (lane >> 4) & 1; ev[4]  += par ? -pr : pr;
        par ^= (lane >> 3) & 1; ev[5]  += par ? -pr : pr;
        par ^= (lane >> 2) & 1; ev[6]  += par ? -pr : pr;
        par ^= (lane >> 1) & 1; ev[7]  += par ? -pr : pr;
        par ^=  lane       & 1; ev[8]  += par ? -pr : pr;
        par ^= (wid  >> 3) & 1; ev[9]  += par ? -pr : pr;
        par ^= (wid  >> 2) & 1; ev[10] += par ? -pr : pr;
        par ^= (wid  >> 1) & 1; ev[11] += par ? -pr : pr;
        par ^=  wid        & 1; ev[12] += par ? -pr : pr;
    }

    #pragma unroll
    for (int q = 0; q < NQ; q++) {
        #pragma unroll
        for (int o = 16; o > 0; o >>= 1)
            ev[q] += __shfl_xor_sync(0xffffffffu, ev[q], o);
    }
    if (lane == 0) {
        #pragma unroll
        for (int q = 0; q < NQ; q++) atomicAdd(&red[q], ev[q]);
    }
    __syncthreads();
    if (t < NQ) out[b * NQ + t] = red[t];
}

extern "C" void kernel_launch(void* const* d_in, const int* in_sizes, int n_in,
                              void* d_out, int out_size)
{
    const float* x = (const float*)d_in[0];   // (B, 13) float32
    const float* w = (const float*)d_in[1];   // (2, 13, 3) float32
    float* out     = (float*)d_out;           // (B, 13) float32

    const int B = in_sizes[0] / NQ;
    const size_t smem = (size_t)DIM * sizeof(float2);   // 64 KB dynamic

    cudaFuncSetAttribute(qsim_kernel,
                         cudaFuncAttributeMaxDynamicSharedMemorySize,
                         (int)smem);
    qsim_kernel<<<B, THREADS, smem>>>(x, w, out);
}

// round 3
// speedup vs baseline: 4.1157x; 1.4191x over previous
#include <cuda_runtime.h>

#define NQ      13
#define NL      2
#define DIM     (1 << NQ)          // 8192 amplitudes
#define THREADS 512
#define PER     16                 // amps per thread

// XOR swizzle -> <=2-phase LDS.64 for both access patterns
__device__ __forceinline__ int swz(int i) { return i ^ ((i >> 4) & 0xF); }

// bit transpose: swap index bits 0..3 <-> 9..12, keep bits 4..8
__device__ __forceinline__ int bitT(int i) {
    return ((i & 0xF) << 9) | (i & 0x1F0) | ((i >> 9) & 0xF);
}

struct C2x2 { float2 u00, u01, u10, u11; };

__device__ __forceinline__ float2 cmul(float2 a, float2 b) {
    return make_float2(fmaf(a.x, b.x, -a.y * b.y),
                       fmaf(a.x, b.y,  a.y * b.x));
}
__device__ __forceinline__ float2 cmad(float2 acc, float2 a, float2 b) {
    acc.x = fmaf(a.x, b.x, fmaf(-a.y, b.y, acc.x));
    acc.y = fmaf(a.x, b.y, fmaf( a.y, b.x, acc.y));
    return acc;
}
__device__ __forceinline__ void gate_pair(float2& a0, float2& a1, const C2x2& U) {
    float2 n0 = cmul(U.u00, a0); n0 = cmad(n0, U.u01, a1);
    float2 n1 = cmul(U.u10, a0); n1 = cmad(n1, U.u11, a1);
    a0 = n0; a1 = n1;
}

__global__ __launch_bounds__(THREADS, 2)
void qsim_kernel(const float* __restrict__ x,
                 const float* __restrict__ w,
                 float* __restrict__ out)
{
    extern __shared__ float2 sbuf[];        // DIM float2 = 64 KB exchange buffer
    __shared__ float uG[NL * NQ][8];        // fused U per (layer,qubit)
    __shared__ float red[NQ];

    const int b    = blockIdx.x;
    const int t    = threadIdx.x;
    const int lane = t & 31;
    const int wid  = t >> 5;                // 0..15

    // ---- precompute all 26 fused U = RZ*RY*RX (one gate per thread) ----
    if (t < NL * NQ) {
        const int l = t / NQ, q = t % NQ;
        const float xv = x[b * NQ + q];
        const float* wr = w + (l * NQ + q) * 3;
        float s1, c1, s2, c2, sp, cp;
        sincosf(0.5f * xv * wr[0], &s1, &c1);   // RX
        sincosf(0.5f * xv * wr[1], &s2, &c2);   // RY
        sincosf(0.5f * wr[2],      &sp, &cp);   // RZ
        float2 m00 = make_float2( c2 * c1,  s2 * s1);
        float2 m01 = make_float2(-s2 * c1, -c2 * s1);
        float2 m10 = make_float2( s2 * c1, -c2 * s1);
        float2 m11 = make_float2( c2 * c1, -s2 * s1);
        const float2 e0 = make_float2(cp, -sp);
        const float2 e1 = make_float2(cp,  sp);
        float2 U00 = cmul(e0, m00), U01 = cmul(e0, m01);
        float2 U10 = cmul(e1, m10), U11 = cmul(e1, m11);
        uG[t][0] = U00.x; uG[t][1] = U00.y;
        uG[t][2] = U01.x; uG[t][3] = U01.y;
        uG[t][4] = U10.x; uG[t][5] = U10.y;
        uG[t][6] = U11.x; uG[t][7] = U11.y;
    }
    if (t < NQ) red[t] = 0.f;
    __syncthreads();   // uG ready

    // ================= LAYER 1 (analytic): state after layer-1 gates is a
    // tensor product of gate first columns; CNOT chain = Gray perm
    // g(i) = i ^ (i>>1). Initialize r[k] = prod of factors at j = g(i),
    // i = (t<<4)|k, bit_b(j) = bit_b(i) ^ bit_{b+1}(i), bit12(j)=bit12(i).
    // Wire q <-> bit (12-q). Wires 0..8 depend only on t; wires 9..12 on k,t0.
    float2 r[PER];
    {
        // base = prod over wires 0..8 of col0 factor
        int sel = (t >> 8) & 1;                          // wire 0: bit12 = t8
        float2 base = make_float2(uG[0][4 * sel], uG[0][4 * sel + 1]);
        #pragma unroll
        for (int q = 1; q <= 8; q++) {
            sel = ((t >> (8 - q)) ^ (t >> (9 - q))) & 1; // t_{8-q} ^ t_{9-q}
            base = cmul(base, make_float2(uG[q][4 * sel], uG[q][4 * sel + 1]));
        }
        // wires 9..12 factors (col 0)
        const float2 f9 [2] = { {uG[ 9][0], uG[ 9][1]}, {uG[ 9][4], uG[ 9][5]} };
        const float2 f10[2] = { {uG[10][0], uG[10][1]}, {uG[10][4], uG[10][5]} };
        const float2 f11[2] = { {uG[11][0], uG[11][1]}, {uG[11][4], uG[11][5]} };
        const float2 f12[2] = { {uG[12][0], uG[12][1]}, {uG[12][4], uG[12][5]} };
        // Q[s9*2+s10] = base*f9*f10 ; P[s11*2+s12] = f11*f12
        float2 b9_0 = cmul(base, f9[0]), b9_1 = cmul(base, f9[1]);
        float2 Q[4] = { cmul(b9_0, f10[0]), cmul(b9_0, f10[1]),
                        cmul(b9_1, f10[0]), cmul(b9_1, f10[1]) };
        float2 P[4] = { cmul(f11[0], f12[0]), cmul(f11[0], f12[1]),
                        cmul(f11[1], f12[0]), cmul(f11[1], f12[1]) };
        const int t0 = t & 1;
        #pragma unroll
        for (int k = 0; k < PER; k++) {
            const int s9  = ((k >> 3) & 1) ^ t0;         // k3 ^ t0
            const int s10 = ((k >> 2) ^ (k >> 3)) & 1;   // k2 ^ k3
            const int s11 = ((k >> 1) ^ (k >> 2)) & 1;   // k1 ^ k2
            const int s12 = ( k       ^ (k >> 1)) & 1;   // k0 ^ k1
            r[k] = cmul(Q[(s9 << 1) | s10], P[(s11 << 1) | s12]);
        }
    }

    // ================= LAYER 2 gates (uG rows 13..25) =================
    // ---- wires 9..12: intra-thread register gates (index bits 3..0) ----
    #pragma unroll
    for (int q = 9; q < NQ; q++) {
        const float* ug = uG[NQ + q];
        C2x2 U = { {ug[0],ug[1]}, {ug[2],ug[3]}, {ug[4],ug[5]}, {ug[6],ug[7]} };
        const int beta = 12 - q;          // 3..0
        #pragma unroll
        for (int m = 0; m < 8; m++) {
            const int k0 = ((m >> beta) << (beta + 1)) | (m & ((1 << beta) - 1));
            const int k1 = k0 | (1 << beta);
            gate_pair(r[k0], r[k1], U);
        }
    }

    // ---- wires 4..8: lane-bit gates via shuffle (index bits 8..4) ----
    #pragma unroll
    for (int q = 4; q < 9; q++) {
        const float* ug = uG[NQ + q];
        C2x2 U = { {ug[0],ug[1]}, {ug[2],ug[3]}, {ug[4],ug[5]}, {ug[6],ug[7]} };
        const int lam = 8 - q;            // 4..0
        const int s   = (lane >> lam) & 1;
        const float2 um = s ? U.u11 : U.u00;   // coeff on my amp
        const float2 uo = s ? U.u10 : U.u01;   // coeff on partner amp
        #pragma unroll
        for (int k = 0; k < PER; k++) {
            float2 o;
            o.x = __shfl_xor_sync(0xffffffffu, r[k].x, 1 << lam);
            o.y = __shfl_xor_sync(0xffffffffu, r[k].y, 1 << lam);
            float2 n = cmul(um, r[k]);
            n = cmad(n, uo, o);
            r[k] = n;
        }
    }

    // ---- bit-transpose pass: u[i'] = v[T(i')] ----
    __syncthreads();
    #pragma unroll
    for (int k = 0; k < PER; k++) sbuf[swz((t << 4) | k)] = r[k];
    __syncthreads();
    #pragma unroll
    for (int k = 0; k < PER; k++) r[k] = sbuf[swz(bitT((t << 4) | k))];

    // ---- wires 0..3: register gates on transposed bits (3-q) ----
    #pragma unroll
    for (int q = 0; q < 4; q++) {
        const float* ug = uG[NQ + q];
        C2x2 U = { {ug[0],ug[1]}, {ug[2],ug[3]}, {ug[4],ug[5]}, {ug[6],ug[7]} };
        const int beta = 3 - q;
        #pragma unroll
        for (int m = 0; m < 8; m++) {
            const int k0 = ((m >> beta) << (beta + 1)) | (m & ((1 << beta) - 1));
            const int k1 = k0 | (1 << beta);
            gate_pair(r[k0], r[k1], U);
        }
    }

    // ---- expvals in transposed layout, folding the final CNOT perm into
    //      the signs. True pre-CNOT index j = T(i'):
    //      j bits: [12..9]=k, [8..4]=lane, [3..0]=wid.
    //      ev[q] sign = parity of bits 12..(12-q) of j (Gray decode). ----
    float ev[NQ];
    #pragma unroll
    for (int q = 0; q < NQ; q++) ev[q] = 0.f;

    #pragma unroll
    for (int k = 0; k < PER; k++) {
        const float2 v = r[k];
        const float pr = fmaf(v.x, v.x, v.y * v.y);
        int par = 0;
        par ^= (k >> 3) & 1;    ev[0]  += par ? -pr : pr;
        par ^= (k >> 2) & 1;    ev[1]  += par ? -pr : pr;
        par ^= (k >> 1) & 1;    ev[2]  += par ? -pr : pr;
        par ^=  k       & 1;    ev[3]  += par ? -pr : pr;
        par ^= (lane >> 4) & 1; ev[4]  += par ? -pr : pr;
        par ^= (lane >> 3) & 1; ev[5]  += par ? -pr : pr;
        par ^= (lane >> 2) & 1; ev[6]  += par ? -pr : pr;
        par ^= (lane >> 1) & 1; ev[7]  += par ? -pr : pr;
        par ^=  lane       & 1; ev[8]  += par ? -pr : pr;
        par ^= (wid  >> 3) & 1; ev[9]  += par ? -pr : pr;
        par ^= (wid  >> 2) & 1; ev[10] += par ? -pr : pr;
        par ^= (wid  >> 1) & 1; ev[11] += par ? -pr : pr;
        par ^=  wid        & 1; ev[12] += par ? -pr : pr;
    }

    #pragma unroll
    for (int q = 0; q < NQ; q++) {
        #pragma unroll
        for (int o = 16; o > 0; o >>= 1)
            ev[q] += __shfl_xor_sync(0xffffffffu, ev[q], o);
    }
    if (lane == 0) {
        #pragma unroll
        for (int q = 0; q < NQ; q++) atomicAdd(&red[q], ev[q]);
    }
    __syncthreads();
    if (t < NQ) out[b * NQ + t] = red[t];
}

extern "C" void kernel_launch(void* const* d_in, const int* in_sizes, int n_in,
                              void* d_out, int out_size)
{
    const float* x = (const float*)d_in[0];   // (B, 13) float32
    const float* w = (const float*)d_in[1];   // (2, 13, 3) float32
    float* out     = (float*)d_out;           // (B, 13) float32

    const int B = in_sizes[0] / NQ;
    const size_t smem = (size_t)DIM * sizeof(float2);   // 64 KB dynamic

    cudaFuncSetAttribute(qsim_kernel,
                         cudaFuncAttributeMaxDynamicSharedMemorySize,
                         (int)smem);
    qsim_kernel<<<B, THREADS, smem>>>(x, w, out);
}

// round 4
// speedup vs baseline: 6.1929x; 1.5047x over previous
#include <cuda_runtime.h>

#define NQ      13
#define DIM     (1 << NQ)
#define THREADS 512
#define PER     16

typedef unsigned long long u64;

// XOR swizzle -> <=2-phase LDS.64
__device__ __forceinline__ int swz(int i) { return i ^ ((i >> 4) & 0xF); }
// bit transpose: swap index bits 0..3 <-> 9..12
__device__ __forceinline__ int bitT(int i) {
    return ((i & 0xF) << 9) | (i & 0x1F0) | ((i >> 9) & 0xF);
}

// ---- packed f32x2 helpers ----
__device__ __forceinline__ u64 pk(float x, float y) {
    u64 r; asm("mov.b64 %0, {%1, %2};" : "=l"(r) : "f"(x), "f"(y)); return r;
}
__device__ __forceinline__ float2 unpk(u64 v) {
    float2 f; asm("mov.b64 {%0, %1}, %2;" : "=f"(f.x), "=f"(f.y) : "l"(v)); return f;
}
__device__ __forceinline__ u64 swp(u64 v) {
    u64 r;
    asm("{\n\t.reg .b32 lo, hi;\n\tmov.b64 {lo, hi}, %1;\n\tmov.b64 %0, {hi, lo};\n\t}"
        : "=l"(r) : "l"(v));
    return r;
}
__device__ __forceinline__ u64 fma2(u64 a, u64 b, u64 c) {
    u64 d; asm("fma.rn.f32x2 %0, %1, %2, %3;" : "=l"(d) : "l"(a), "l"(b), "l"(c)); return d;
}
__device__ __forceinline__ u64 mul2(u64 a, u64 b) {
    u64 d; asm("mul.rn.f32x2 %0, %1, %2;" : "=l"(d) : "l"(a), "l"(b)); return d;
}

// packed gate coeffs: d = (ux,ux), s = (-uy, uy) for each of 4 entries
struct GateP { u64 d00, s00, d01, s01, d10, s10, d11, s11; };

__device__ __forceinline__ GateP load_gate(const float* ug) {
    GateP g;
    g.d00 = pk(ug[0], ug[0]); g.s00 = pk(-ug[1], ug[1]);
    g.d01 = pk(ug[2], ug[2]); g.s01 = pk(-ug[3], ug[3]);
    g.d10 = pk(ug[4], ug[4]); g.s10 = pk(-ug[5], ug[5]);
    g.d11 = pk(ug[6], ug[6]); g.s11 = pk(-ug[7], ug[7]);
    return g;
}

// (a0,a1) <- U*(a0,a1), packed complex math
__device__ __forceinline__ void gate_pair_p(u64& a0, u64& a1, const GateP& g) {
    const u64 a0s = swp(a0), a1s = swp(a1);
    u64 t = mul2(a1s, g.s01);
    t = fma2(a1, g.d01, t);
    t = fma2(a0s, g.s00, t);
    const u64 n0 = fma2(a0, g.d00, t);
    u64 u = mul2(a1s, g.s11);
    u = fma2(a1, g.d11, u);
    u = fma2(a0s, g.s10, u);
    const u64 n1 = fma2(a0, g.d10, u);
    a0 = n0; a1 = n1;
}

// scalar complex helpers (init only)
__device__ __forceinline__ float2 cmul(float2 a, float2 b) {
    return make_float2(fmaf(a.x, b.x, -a.y * b.y),
                       fmaf(a.x, b.y,  a.y * b.x));
}

__global__ __launch_bounds__(THREADS, 2)
void qsim_kernel(const float* __restrict__ x,
                 const float* __restrict__ w,
                 float* __restrict__ out)
{
    extern __shared__ u64 sbuf[];           // DIM u64 = 64 KB exchange buffer
    __shared__ float uG[2 * NQ][8];
    __shared__ float red[NQ];

    const int b    = blockIdx.x;
    const int t    = threadIdx.x;
    const int lane = t & 31;
    const int wid  = t >> 5;

    // ---- precompute all 26 fused U = RZ*RY*RX ----
    if (t < 2 * NQ) {
        const int l = t / NQ, q = t % NQ;
        const float xv = x[b * NQ + q];
        const float* wr = w + (l * NQ + q) * 3;
        float s1, c1, s2, c2, sp, cp;
        sincosf(0.5f * xv * wr[0], &s1, &c1);
        sincosf(0.5f * xv * wr[1], &s2, &c2);
        sincosf(0.5f * wr[2],      &sp, &cp);
        float2 m00 = make_float2( c2 * c1,  s2 * s1);
        float2 m01 = make_float2(-s2 * c1, -c2 * s1);
        float2 m10 = make_float2( s2 * c1, -c2 * s1);
        float2 m11 = make_float2( c2 * c1, -s2 * s1);
        const float2 e0 = make_float2(cp, -sp);
        const float2 e1 = make_float2(cp,  sp);
        float2 U00 = cmul(e0, m00), U01 = cmul(e0, m01);
        float2 U10 = cmul(e1, m10), U11 = cmul(e1, m11);
        uG[t][0] = U00.x; uG[t][1] = U00.y;
        uG[t][2] = U01.x; uG[t][3] = U01.y;
        uG[t][4] = U10.x; uG[t][5] = U10.y;
        uG[t][6] = U11.x; uG[t][7] = U11.y;
    }
    if (t < NQ) red[t] = 0.f;
    __syncthreads();

    // ---- LAYER 1 analytic init (tensor product + Gray perm baked in) ----
    u64 r[PER];
    {
        int sel = (t >> 8) & 1;
        float2 base = make_float2(uG[0][4 * sel], uG[0][4 * sel + 1]);
        #pragma unroll
        for (int q = 1; q <= 8; q++) {
            sel = ((t >> (8 - q)) ^ (t >> (9 - q))) & 1;
            base = cmul(base, make_float2(uG[q][4 * sel], uG[q][4 * sel + 1]));
        }
        const float2 f9 [2] = { {uG[ 9][0], uG[ 9][1]}, {uG[ 9][4], uG[ 9][5]} };
        const float2 f10[2] = { {uG[10][0], uG[10][1]}, {uG[10][4], uG[10][5]} };
        const float2 f11[2] = { {uG[11][0], uG[11][1]}, {uG[11][4], uG[11][5]} };
        const float2 f12[2] = { {uG[12][0], uG[12][1]}, {uG[12][4], uG[12][5]} };
        float2 b9_0 = cmul(base, f9[0]), b9_1 = cmul(base, f9[1]);
        float2 Q[4] = { cmul(b9_0, f10[0]), cmul(b9_0, f10[1]),
                        cmul(b9_1, f10[0]), cmul(b9_1, f10[1]) };
        float2 P[4] = { cmul(f11[0], f12[0]), cmul(f11[0], f12[1]),
                        cmul(f11[1], f12[0]), cmul(f11[1], f12[1]) };
        const int t0 = t & 1;
        #pragma unroll
        for (int k = 0; k < PER; k++) {
            const int s9  = ((k >> 3) & 1) ^ t0;
            const int s10 = ((k >> 2) ^ (k >> 3)) & 1;
            const int s11 = ((k >> 1) ^ (k >> 2)) & 1;
            const int s12 = ( k       ^ (k >> 1)) & 1;
            float2 v = cmul(Q[(s9 << 1) | s10], P[(s11 << 1) | s12]);
            r[k] = pk(v.x, v.y);
        }
    }

    // ================= LAYER 2 gates (uG rows 13..25) =================
    // wires 9..12: intra-thread gates on k bits 3..0
    #pragma unroll
    for (int q = 9; q < NQ; q++) {
        const GateP g = load_gate(uG[NQ + q]);
        const int beta = 12 - q;
        #pragma unroll
        for (int m = 0; m < 8; m++) {
            const int k0 = ((m >> beta) << (beta + 1)) | (m & ((1 << beta) - 1));
            gate_pair_p(r[k0], r[k0 | (1 << beta)], g);
        }
    }

    // wires 4..8: lane-bit gates via shuffle
    #pragma unroll
    for (int q = 4; q < 9; q++) {
        const float* ug = uG[NQ + q];
        const int lam = 8 - q;
        const int s   = (lane >> lam) & 1;
        // my coeff um = s? U11:U00 ; partner coeff uo = s? U10:U01
        const float umx = s ? ug[6] : ug[0], umy = s ? ug[7] : ug[1];
        const float uox = s ? ug[4] : ug[2], uoy = s ? ug[5] : ug[3];
        const u64 umd = pk(umx, umx), ums = pk(-umy, umy);
        const u64 uod = pk(uox, uox), uos = pk(-uoy, uoy);
        #pragma unroll
        for (int k = 0; k < PER; k++) {
            const u64 o  = __shfl_xor_sync(0xffffffffu, r[k], 1 << lam);
            const u64 rs = swp(r[k]), os = swp(o);
            u64 tt = mul2(os, uos);
            tt = fma2(o, uod, tt);
            tt = fma2(rs, ums, tt);
            r[k] = fma2(r[k], umd, tt);
        }
    }

    // ---- bit-transpose pass ----
    __syncthreads();
    #pragma unroll
    for (int k = 0; k < PER; k++) sbuf[swz((t << 4) | k)] = r[k];
    __syncthreads();
    #pragma unroll
    for (int k = 0; k < PER; k++) r[k] = sbuf[swz(bitT((t << 4) | k))];

    // wires 0..3: gates on transposed bits
    #pragma unroll
    for (int q = 0; q < 4; q++) {
        const GateP g = load_gate(uG[NQ + q]);
        const int beta = 3 - q;
        #pragma unroll
        for (int m = 0; m < 8; m++) {
            const int k0 = ((m >> beta) << (beta + 1)) | (m & ((1 << beta) - 1));
            gate_pair_p(r[k0], r[k0 | (1 << beta)], g);
        }
    }

    // ================= epilogue: Walsh butterflies =================
    // per-thread probabilities
    float pr[PER];
    #pragma unroll
    for (int k = 0; k < PER; k++) {
        const float2 v = unpk(r[k]);
        pr[k] = fmaf(v.x, v.x, v.y * v.y);
    }
    // intra-thread prefix-parity Walsh over k bits (j bits 12..9):
    float a_[8], b_[8];
    #pragma unroll
    for (int m = 0; m < 8; m++) { a_[m] = pr[2*m] + pr[2*m+1]; b_[m] = pr[2*m] - pr[2*m+1]; }
    float a2[4], c2[4], d2[4];
    #pragma unroll
    for (int n = 0; n < 4; n++) {
        a2[n] = a_[2*n] + a_[2*n+1];
        c2[n] = a_[2*n] - a_[2*n+1];
        d2[n] = b_[2*n] - b_[2*n+1];
    }
    const float P0 = (a2[0] + a2[1]) - (a2[2] + a2[3]);          // sign k3
    const float P1 =  a2[0] - a2[1] - a2[2] + a2[3];             // k3^k2
    const float P2 =  c2[0] - c2[1] - c2[2] + c2[3];             // k3^k2^k1
    const float P3 =  d2[0] - d2[1] - d2[2] + d2[3];             // parity(k)

    // warp stage: prefix diff-chain over lane bits 4..0 on P3,
    // plus plain sums of P0,P1,P2,P3. All values valid at lane 0.
    const unsigned FULL = 0xffffffffu;
    float s0 = P0, s1 = P1, s2 = P2;
    #pragma unroll
    for (int o = 16; o > 0; o >>= 1) {
        s0 += __shfl_xor_sync(FULL, s0, o);
        s1 += __shfl_xor_sync(FULL, s1, o);
        s2 += __shfl_xor_sync(FULL, s2, o);
    }
    const float t4 = __shfl_xor_sync(FULL, P3, 16);
    float c4w = P3 - t4;                   // sign lane4
    float Dw  = P3 + t4;                   // plain
    #pragma unroll
    for (int o = 8; o > 0; o >>= 1) Dw += __shfl_xor_sync(FULL, Dw, o);

    const float c3w = c4w - __shfl_xor_sync(FULL, c4w, 8);   // +lane3
    const float c2w = c3w - __shfl_xor_sync(FULL, c3w, 4);   // +lane2
    const float c1w = c2w - __shfl_xor_sync(FULL, c2w, 2);   // +lane1
    const float c0w = c1w - __shfl_xor_sync(FULL, c1w, 1);   // +lane0 -> ev8

    float e7 = c1w + __shfl_xor_sync(FULL, c1w, 1);
    float e6 = c2w + __shfl_xor_sync(FULL, c2w, 2);
    e6 += __shfl_xor_sync(FULL, e6, 1);
    float e5 = c3w + __shfl_xor_sync(FULL, c3w, 4);
    e5 += __shfl_xor_sync(FULL, e5, 2);
    e5 += __shfl_xor_sync(FULL, e5, 1);
    float e4 = c4w + __shfl_xor_sync(FULL, c4w, 8);
    e4 += __shfl_xor_sync(FULL, e4, 4);
    e4 += __shfl_xor_sync(FULL, e4, 2);
    e4 += __shfl_xor_sync(FULL, e4, 1);

    if (lane == 0) {
        atomicAdd(&red[0], s0);
        atomicAdd(&red[1], s1);
        atomicAdd(&red[2], s2);
        atomicAdd(&red[3], Dw);
        atomicAdd(&red[4], e4);
        atomicAdd(&red[5], e5);
        atomicAdd(&red[6], e6);
        atomicAdd(&red[7], e7);
        atomicAdd(&red[8], c0w);
        int p = (wid >> 3) & 1;
        atomicAdd(&red[9],  p ? -c0w : c0w);
        p ^= (wid >> 2) & 1;
        atomicAdd(&red[10], p ? -c0w : c0w);
        p ^= (wid >> 1) & 1;
        atomicAdd(&red[11], p ? -c0w : c0w);
        p ^= wid & 1;
        atomicAdd(&red[12], p ? -c0w : c0w);
    }
    __syncthreads();
    if (t < NQ) out[b * NQ + t] = red[t];
}

extern "C" void kernel_launch(void* const* d_in, const int* in_sizes, int n_in,
                              void* d_out, int out_size)
{
    const float* x = (const float*)d_in[0];
    const float* w = (const float*)d_in[1];
    float* out     = (float*)d_out;

    const int B = in_sizes[0] / NQ;
    const size_t smem = (size_t)DIM * sizeof(u64);   // 64 KB dynamic

    cudaFuncSetAttribute(qsim_kernel,
                         cudaFuncAttributeMaxDynamicSharedMemorySize,
                         (int)smem);
    qsim_kernel<<<B, THREADS, smem>>>(x, w, out);
}

// round 5
// speedup vs baseline: 19.3529x; 3.1250x over previous
#include <cuda_runtime.h>

#define NQ 13

// Transfer-matrix contraction of the whole circuit.
// ev[q] = <0| G1+ C+ G2+ C+ Z_q C G2 C G1 |0>
//  - C+ Z_q C = prefix Z-string over wires 0..q
//  - G2+ (prefix Z) G2 = tensor product of M_w = U2_w+ Z U2_w
//  - |chi> = G1|0> = product of first columns phi_w
//  - C = Gray perm: bit coupling chi(g(i))_b depends on (i_b, i_{b+1})
// => nearest-neighbor chain, bond = (i_b, i'_b) in {0,1}^2, Hermitian-reduced
//    state: v00, v11 real; v01 complex.
// Unprocessed identity wires telescope to 1 by unitarity; the first identity
// wire leaves boundary factor K(a,a') = 1 (a==a') / kappa (a!=a'),
// kappa_w = 2 Re(conj(phi_w(0)) phi_w(1)).
__global__ void qsim_tn(const float* __restrict__ x,
                        const float* __restrict__ wts,
                        float* __restrict__ out,
                        int n)
{
    const int e = blockIdx.x * blockDim.x + threadIdx.x;
    if (e >= n) return;

    float v00 = 0.f, v11 = 0.f, v01x = 0.f, v01y = 0.f;

    #pragma unroll 1
    for (int q = 0; q < NQ; q++) {
        const float xv = x[e * NQ + q];

        // ---- layer-1 fused gate U = RZ*RY*RX, column 0 -> phi = (p0, p1) ----
        const float* w1 = wts + q * 3;
        float s1, c1, s2, c2, sp, cp;
        __sincosf(0.5f * xv * w1[0], &s1, &c1);   // RX half-angle
        __sincosf(0.5f * xv * w1[1], &s2, &c2);   // RY half-angle
        __sincosf(0.5f * w1[2],      &sp, &cp);   // RZ half-angle
        // m00 = (c2c1, s2s1), m10 = (s2c1, -c2s1); U00=(cp,-sp)*m00, U10=(cp,sp)*m10
        const float p0x = fmaf(cp, c2 * c1,  sp * (s2 * s1));
        const float p0y = fmaf(cp, s2 * s1, -sp * (c2 * c1));
        const float p1x = fmaf(cp, s2 * c1,  sp * (c2 * s1));
        const float p1y = fmaf(sp, s2 * c1, -cp * (c2 * s1));
        const float kap = 2.f * fmaf(p0x, p1x, p0y * p1y);

        // ---- emit ev[q-1]: uses v after wire q-1 and kappa of wire q ----
        if (q > 0)
            out[e * NQ + (q - 1)] = v00 + v11 + kap * (2.f * v01x);

        // ---- layer-2 fused gate (full 2x2) -> M = [[m, mu],[mu*, -m]] ----
        const float* w2 = wts + (NQ + q) * 3;
        __sincosf(0.5f * xv * w2[0], &s1, &c1);
        __sincosf(0.5f * xv * w2[1], &s2, &c2);
        __sincosf(0.5f * w2[2],      &sp, &cp);
        const float m00x = c2 * c1, m00y =  s2 * s1;
        const float m01x = -s2 * c1, m01y = -c2 * s1;
        const float m10x =  s2 * c1, m10y = -c2 * s1;
        const float m11x =  c2 * c1, m11y = -s2 * s1;
        // U00=(cp,-sp)*m00, U01=(cp,-sp)*m01, U10=(cp,sp)*m10, U11=(cp,sp)*m11
        const float u00x = fmaf(cp, m00x,  sp * m00y), u00y = fmaf(cp, m00y, -sp * m00x);
        const float u01x = fmaf(cp, m01x,  sp * m01y), u01y = fmaf(cp, m01y, -sp * m01x);
        const float u10x = fmaf(cp, m10x, -sp * m10y), u10y = fmaf(cp, m10y,  sp * m10x);
        const float u11x = fmaf(cp, m11x, -sp * m11y), u11y = fmaf(cp, m11y,  sp * m11x);
        const float m   = fmaf(2.f, fmaf(u00x, u00x, u00y * u00y), -1.f);
        // mu = conj(u00)*u01 - conj(u10)*u11
        const float mux = (u00x * u01x + u00y * u01y) - (u10x * u11x + u10y * u11y);
        const float muy = (u00x * u01y - u00y * u01x) - (u10x * u11y - u10y * u11x);

        if (q == 0) {
            // v(a,a') = conj(phi(a)) M(a,a') phi(a')
            v00  =  m * fmaf(p0x, p0x, p0y * p0y);
            v11  = -m * fmaf(p1x, p1x, p1y * p1y);
            const float tx = fmaf(p0x, p1x,  p0y * p1y);   // conj(p0)*p1
            const float ty = fmaf(p0x, p1y, -p0y * p1x);
            v01x = fmaf(mux, tx, -muy * ty);
            v01y = fmaf(mux, ty,  muy * tx);
        } else {
            // h(c,a') = sum_{c'} phi(a'^c') v(c,c')
            const float h00x = fmaf(p0x, v00, fmaf(p1x, v01x, -p1y * v01y));
            const float h00y = fmaf(p0y, v00, fmaf(p1x, v01y,  p1y * v01x));
            const float h01x = fmaf(p1x, v00, fmaf(p0x, v01x, -p0y * v01y));
            const float h01y = fmaf(p1y, v00, fmaf(p0x, v01y,  p0y * v01x));
            const float h10x = fmaf(p1x, v11, fmaf(p0x, v01x,  p0y * v01y));
            const float h10y = fmaf(p1y, v11, fmaf(p0y, v01x, -p0x * v01y));
            const float h11x = fmaf(p0x, v11, fmaf(p1x, v01x,  p1y * v01y));
            const float h11y = fmaf(p0y, v11, fmaf(p1y, v01x, -p1x * v01y));
            // w(a,a') = sum_c conj(phi(a^c)) h(c,a')
            const float w00  = fmaf(p0x, h00x, p0y * h00y) + fmaf(p1x, h10x, p1y * h10y);
            const float w01x = fmaf(p0x, h01x, p0y * h01y) + fmaf(p1x, h11x, p1y * h11y);
            const float w01y = fmaf(p0x, h01y, -p0y * h01x) + fmaf(p1x, h11y, -p1y * h11x);
            const float w11  = fmaf(p1x, h01x, p1y * h01y) + fmaf(p0x, h11x, p0y * h11y);
            // v_new = M .* w  (elementwise per bond entry)
            v00  =  m * w00;
            v11  = -m * w11;
            v01x = fmaf(mux, w01x, -muy * w01y);
            v01y = fmaf(mux, w01y,  muy * w01x);
        }
    }

    out[e * NQ + (NQ - 1)] = v00 + v11 + 2.f * v01x;
}

extern "C" void kernel_launch(void* const* d_in, const int* in_sizes, int n_in,
                              void* d_out, int out_size)
{
    const float* x = (const float*)d_in[0];   // (B, 13) float32
    const float* w = (const float*)d_in[1];   // (2, 13, 3) float32
    float* out     = (float*)d_out;           // (B, 13) float32

    const int B = in_sizes[0] / NQ;           // 512
    const int TPB = 32;
    const int grid = (B + TPB - 1) / TPB;     // 16 blocks -> 16 SMs, 1 warp each
    qsim_tn<<<grid, TPB>>>(x, w, out, B);
}